// round 4
// baseline (speedup 1.0000x reference)
#include <cuda_runtime.h>
#include <cuda_bf16.h>
#include <stdint.h>

// ---------------------------------------------------------------------------
// GCN 2-layer:
//   h1  = x @ W1                      [N,128]
//   agg = scatter_add(h1[src] -> dst) [N,128]
//   h2  = relu(agg) @ W2              [N,40]
//   out = scatter_add(h2[src] -> dst) [N,40]
// N = 100000, E = 1600000, x/W fp32, edge_index int32 (JAX x64 disabled
// downcasts the requested int64 to int32).
// ---------------------------------------------------------------------------

#define N_NODES 100000
#define N_EDGES 1600000

// Scratch (device globals: allocation-free per harness rules)
__device__ float g_h1[N_NODES * 128];   // 51.2 MB
__device__ float g_agg[N_NODES * 128];  // 51.2 MB
__device__ float g_h2[N_NODES * 40];    // 16.0 MB

// ---------------------------------------------------------------------------
// helpers
// ---------------------------------------------------------------------------
__device__ __forceinline__ void red_add_v4(float* addr, float4 v) {
    asm volatile("red.global.add.v4.f32 [%0], {%1, %2, %3, %4};"
                 :: "l"(addr), "f"(v.x), "f"(v.y), "f"(v.z), "f"(v.w)
                 : "memory");
}

// ---------------------------------------------------------------------------
// zero kernels
// ---------------------------------------------------------------------------
__global__ void zero_agg_kernel() {
    int i = blockIdx.x * blockDim.x + threadIdx.x;
    int n4 = N_NODES * 128 / 4;
    if (i < n4) ((float4*)g_agg)[i] = make_float4(0.f, 0.f, 0.f, 0.f);
}

__global__ void zero_out_kernel(float4* __restrict__ p, int n4) {
    int i = blockIdx.x * blockDim.x + threadIdx.x;
    if (i < n4) p[i] = make_float4(0.f, 0.f, 0.f, 0.f);
}

// ---------------------------------------------------------------------------
// GEMM1: h1[N,128] = x[N,256] @ W1[256,128]
// BM=64, BN=128, BK=16, 256 threads, micro-tile TM=8 x TN=4.
// A reads from smem are warp-broadcast (all lanes in a warp share ty).
// ---------------------------------------------------------------------------
__global__ __launch_bounds__(256, 4)
void gemm1_kernel(const float* __restrict__ X, const float* __restrict__ W, int N) {
    __shared__ float As[64][16];
    __shared__ float Bs[16][128];

    const int tid = threadIdx.x;
    const int tx  = tid & 31;   // col group: cols [tx*4, tx*4+4)
    const int ty  = tid >> 5;   // row group: rows [ty*8, ty*8+8)
    const int block_row = blockIdx.x * 64;

    // A-load mapping: each thread loads one float4
    const int arow = tid >> 2;          // 0..63
    const int acol = (tid & 3) << 2;    // 0,4,8,12
    // B-load mapping: each thread loads two float4
    const int brow = tid >> 4;          // 0..15
    const int bcol = (tid & 15) << 3;   // 0..120

    float acc[8][4];
    #pragma unroll
    for (int i = 0; i < 8; i++)
        #pragma unroll
        for (int j = 0; j < 4; j++) acc[i][j] = 0.f;

    for (int k0 = 0; k0 < 256; k0 += 16) {
        // load A tile
        int grow = block_row + arow;
        float4 av = make_float4(0.f, 0.f, 0.f, 0.f);
        if (grow < N) av = *(const float4*)(X + (size_t)grow * 256 + k0 + acol);
        *(float4*)&As[arow][acol] = av;
        // load B tile (W1 row-major [256][128])
        const float* wb = W + (size_t)(k0 + brow) * 128 + bcol;
        *(float4*)&Bs[brow][bcol]     = *(const float4*)(wb);
        *(float4*)&Bs[brow][bcol + 4] = *(const float4*)(wb + 4);
        __syncthreads();

        #pragma unroll
        for (int k = 0; k < 16; k++) {
            float a[8];
            #pragma unroll
            for (int i = 0; i < 8; i++) a[i] = As[ty * 8 + i][k];   // broadcast
            float4 b = *(const float4*)&Bs[k][tx * 4];
            #pragma unroll
            for (int i = 0; i < 8; i++) {
                acc[i][0] += a[i] * b.x;
                acc[i][1] += a[i] * b.y;
                acc[i][2] += a[i] * b.z;
                acc[i][3] += a[i] * b.w;
            }
        }
        __syncthreads();
    }

    #pragma unroll
    for (int i = 0; i < 8; i++) {
        int grow = block_row + ty * 8 + i;
        if (grow < N) {
            float4 v = make_float4(acc[i][0], acc[i][1], acc[i][2], acc[i][3]);
            *(float4*)(g_h1 + (size_t)grow * 128 + tx * 4) = v;
        }
    }
}

// ---------------------------------------------------------------------------
// Scatter layer 1: agg[dst] += h1[src]  (width 128, one warp per edge,
// each lane handles one float4 and issues one 16B vector reduction)
// ---------------------------------------------------------------------------
__global__ __launch_bounds__(256)
void scatter1_kernel(const int* __restrict__ ei, int E) {
    int warp = blockIdx.x * (blockDim.x >> 5) + (threadIdx.x >> 5);
    if (warp >= E) return;
    int lane = threadIdx.x & 31;
    int src = __ldg(&ei[warp]);
    int dst = __ldg(&ei[E + warp]);
    float4 v = *(const float4*)(g_h1 + (size_t)src * 128 + lane * 4);
    red_add_v4(g_agg + (size_t)dst * 128 + lane * 4, v);
}

// ---------------------------------------------------------------------------
// GEMM2: h2[N,40] = relu(agg[N,128]) @ W2[128,40]
// Block handles 32 rows. Ws reads are warp-broadcast; As reads conflict-free
// via 129-float row stride.
// ---------------------------------------------------------------------------
__global__ __launch_bounds__(256)
void gemm2_kernel(const float* __restrict__ W2, int N) {
    __shared__ float Ws[128 * 40];   // 20 KB
    __shared__ float As[32][129];    // ~16.5 KB, pad for conflict-free column reads

    const int t = threadIdx.x;
    const int row0 = blockIdx.x * 32;

    for (int i = t; i < 128 * 40; i += 256) Ws[i] = W2[i];

    #pragma unroll
    for (int i = 0; i < 4; i++) {
        int lin = t + i * 256;          // float4 index in [0,1024)
        int r   = lin >> 5;             // row in tile
        int c4  = (lin & 31) << 2;      // col (float index)
        int grow = row0 + r;
        float4 v = make_float4(0.f, 0.f, 0.f, 0.f);
        if (grow < N) v = *(const float4*)(g_agg + (size_t)grow * 128 + c4);
        As[r][c4 + 0] = fmaxf(v.x, 0.f);
        As[r][c4 + 1] = fmaxf(v.y, 0.f);
        As[r][c4 + 2] = fmaxf(v.z, 0.f);
        As[r][c4 + 3] = fmaxf(v.w, 0.f);
    }
    __syncthreads();

    const int r     = t & 31;    // lane -> row (conflict-free As column reads)
    const int cbase = t >> 5;    // 0..7; cols cbase + 8*i  (broadcast Ws reads)

    float sum[5] = {0.f, 0.f, 0.f, 0.f, 0.f};
    #pragma unroll 8
    for (int k = 0; k < 128; k++) {
        float a = As[r][k];
        #pragma unroll
        for (int i = 0; i < 5; i++)
            sum[i] += a * Ws[k * 40 + cbase + i * 8];
    }

    int grow = row0 + r;
    if (grow < N) {
        #pragma unroll
        for (int i = 0; i < 5; i++)
            g_h2[(size_t)grow * 40 + cbase + i * 8] = sum[i];
    }
}

// ---------------------------------------------------------------------------
// Scatter layer 2: out[dst] += h2[src] (width 40 = 10 float4 per edge)
// ---------------------------------------------------------------------------
__global__ __launch_bounds__(256)
void scatter2_kernel(const int* __restrict__ ei, int E,
                     float* __restrict__ OUT) {
    long long idx = (long long)blockIdx.x * blockDim.x + threadIdx.x;
    if (idx >= (long long)E * 10) return;
    int e = (int)(idx / 10);
    int c = (int)(idx - (long long)e * 10);
    int src = __ldg(&ei[e]);
    int dst = __ldg(&ei[E + e]);
    float4 v = *(const float4*)(g_h2 + (size_t)src * 40 + c * 4);
    red_add_v4(OUT + (size_t)dst * 40 + c * 4, v);
}

// ---------------------------------------------------------------------------
// launch
// ---------------------------------------------------------------------------
extern "C" void kernel_launch(void* const* d_in, const int* in_sizes, int n_in,
                              void* d_out, int out_size) {
    const float* x  = (const float*)d_in[0];
    const int*   ei = (const int*)d_in[1];     // int32: JAX x64-disabled downcast
    const float* W1 = (const float*)d_in[2];
    const float* W2 = (const float*)d_in[3];
    float* out = (float*)d_out;

    const int N = in_sizes[0] / 256;
    const int E = in_sizes[1] / 2;

    // zero accumulation buffers (d_out is poisoned by harness)
    {
        int n4 = N_NODES * 128 / 4;
        zero_agg_kernel<<<(n4 + 255) / 256, 256>>>();
        int o4 = N * 40 / 4;
        zero_out_kernel<<<(o4 + 255) / 256, 256>>>((float4*)out, o4);
    }

    // layer 1: transform
    gemm1_kernel<<<(N + 63) / 64, 256>>>(x, W1, N);
    // layer 1: aggregate (one warp per edge)
    {
        long long total_threads = (long long)E * 32;
        int blocks = (int)((total_threads + 255) / 256);
        scatter1_kernel<<<blocks, 256>>>(ei, E);
    }
    // layer 2: relu + transform
    gemm2_kernel<<<(N + 31) / 32, 256>>>(W2, N);
    // layer 2: aggregate into output
    {
        long long total = (long long)E * 10;
        int blocks = (int)((total + 255) / 256);
        scatter2_kernel<<<blocks, 256>>>(ei, E, out);
    }
}

// round 5
// speedup vs baseline: 1.1394x; 1.1394x over previous
#include <cuda_runtime.h>
#include <cuda_bf16.h>
#include <stdint.h>

// ---------------------------------------------------------------------------
// GCN 2-layer:
//   h1  = x @ W1                      [N,128]
//   agg = scatter_add(h1[src] -> dst) [N,128]
//   h2  = relu(agg) @ W2              [N,40]
//   out = scatter_add(h2[src] -> dst) [N,40]
// N = 100000, E = 1600000, x/W fp32, edge_index int32.
// ---------------------------------------------------------------------------

#define N_NODES 100000
#define N_EDGES 1600000

__device__ float g_h1[N_NODES * 128];   // 51.2 MB
__device__ float g_agg[N_NODES * 128];  // 51.2 MB
__device__ float g_h2[N_NODES * 40];    // 16.0 MB

// ---------------------------------------------------------------------------
// helpers
// ---------------------------------------------------------------------------
__device__ __forceinline__ void red_add_v4(float* addr, float4 v) {
    asm volatile("red.global.add.v4.f32 [%0], {%1, %2, %3, %4};"
                 :: "l"(addr), "f"(v.x), "f"(v.y), "f"(v.z), "f"(v.w)
                 : "memory");
}

__device__ __forceinline__ unsigned long long pack2(float x, float y) {
    unsigned long long r;
    asm("mov.b64 %0, {%1, %2};" : "=l"(r) : "f"(x), "f"(y));
    return r;
}
__device__ __forceinline__ void unpack2(unsigned long long p, float& x, float& y) {
    asm("mov.b64 {%0, %1}, %2;" : "=f"(x), "=f"(y) : "l"(p));
}
// packed dual fp32 FMA (sm_103a): c = a*b + c, elementwise on 2 floats
__device__ __forceinline__ void fma2(unsigned long long& c,
                                     unsigned long long a,
                                     unsigned long long b) {
    asm("fma.rn.f32x2 %0, %1, %2, %0;" : "+l"(c) : "l"(a), "l"(b));
}

// ---------------------------------------------------------------------------
// zero kernels
// ---------------------------------------------------------------------------
__global__ void zero_agg_kernel() {
    int i = blockIdx.x * blockDim.x + threadIdx.x;
    int n4 = N_NODES * 128 / 4;
    if (i < n4) ((float4*)g_agg)[i] = make_float4(0.f, 0.f, 0.f, 0.f);
}

__global__ void zero_out_kernel(float4* __restrict__ p, int n4) {
    int i = blockIdx.x * blockDim.x + threadIdx.x;
    if (i < n4) p[i] = make_float4(0.f, 0.f, 0.f, 0.f);
}

// ---------------------------------------------------------------------------
// GEMM1: h1[N,128] = x[N,256] @ W1[256,128]
// BM=64, BN=128, BK=16, 256 threads, micro-tile 8x4, packed f32x2 FMAs.
// A tile stored k-major (transposed) so the 8 row-operands per k are two
// broadcast LDS.128.
// ---------------------------------------------------------------------------
__global__ __launch_bounds__(256, 4)
void gemm1_kernel(const float* __restrict__ X, const float* __restrict__ W, int N) {
    __shared__ float At[16][68];    // [k][row], padded
    __shared__ float Bs[16][128];

    const int tid = threadIdx.x;
    const int tx  = tid & 31;   // col group: cols [tx*4, tx*4+4)
    const int ty  = tid >> 5;   // row group: rows [ty*8, ty*8+8)
    const int block_row = blockIdx.x * 64;

    const int arow = tid >> 2;          // 0..63
    const int acol = (tid & 3) << 2;    // 0,4,8,12
    const int brow = tid >> 4;          // 0..15
    const int bcol = (tid & 15) << 3;   // 0..120

    unsigned long long acc2[8][2];
    #pragma unroll
    for (int i = 0; i < 8; i++) { acc2[i][0] = 0ull; acc2[i][1] = 0ull; }

    for (int k0 = 0; k0 < 256; k0 += 16) {
        // load A tile (transposed into At[k][row])
        int grow = block_row + arow;
        float4 av = make_float4(0.f, 0.f, 0.f, 0.f);
        if (grow < N) av = *(const float4*)(X + (size_t)grow * 256 + k0 + acol);
        At[acol + 0][arow] = av.x;
        At[acol + 1][arow] = av.y;
        At[acol + 2][arow] = av.z;
        At[acol + 3][arow] = av.w;
        // load B tile (W1 row-major [256][128])
        const float* wb = W + (size_t)(k0 + brow) * 128 + bcol;
        *(float4*)&Bs[brow][bcol]     = *(const float4*)(wb);
        *(float4*)&Bs[brow][bcol + 4] = *(const float4*)(wb + 4);
        __syncthreads();

        #pragma unroll
        for (int k = 0; k < 16; k++) {
            float4 a0 = *(const float4*)&At[k][ty * 8];      // broadcast
            float4 a1 = *(const float4*)&At[k][ty * 8 + 4];  // broadcast
            float4 b  = *(const float4*)&Bs[k][tx * 4];
            unsigned long long b01 = pack2(b.x, b.y);
            unsigned long long b23 = pack2(b.z, b.w);
            float a[8] = {a0.x, a0.y, a0.z, a0.w, a1.x, a1.y, a1.z, a1.w};
            #pragma unroll
            for (int i = 0; i < 8; i++) {
                unsigned long long ap = pack2(a[i], a[i]);
                fma2(acc2[i][0], ap, b01);
                fma2(acc2[i][1], ap, b23);
            }
        }
        __syncthreads();
    }

    #pragma unroll
    for (int i = 0; i < 8; i++) {
        int grow = block_row + ty * 8 + i;
        if (grow < N) {
            float4 v;
            unpack2(acc2[i][0], v.x, v.y);
            unpack2(acc2[i][1], v.z, v.w);
            *(float4*)(g_h1 + (size_t)grow * 128 + tx * 4) = v;
        }
    }
}

// ---------------------------------------------------------------------------
// Scatter layer 1: agg[dst] += h1[src]  (width 128).
// 4 edges per warp: uniform int4 index loads, 4 independent gathers
// front-batched (MLP=4), then 4 vector reductions.
// ---------------------------------------------------------------------------
__global__ __launch_bounds__(256)
void scatter1_kernel(const int* __restrict__ ei, int E) {
    int warp = blockIdx.x * (blockDim.x >> 5) + (threadIdx.x >> 5);
    int lane = threadIdx.x & 31;
    int e0 = warp * 4;
    if (e0 >= E) return;

    if (e0 + 4 <= E) {
        int4 s4 = __ldg((const int4*)(ei + e0));
        int4 d4 = __ldg((const int4*)(ei + E + e0));
        float4 v0 = *(const float4*)(g_h1 + (size_t)s4.x * 128 + lane * 4);
        float4 v1 = *(const float4*)(g_h1 + (size_t)s4.y * 128 + lane * 4);
        float4 v2 = *(const float4*)(g_h1 + (size_t)s4.z * 128 + lane * 4);
        float4 v3 = *(const float4*)(g_h1 + (size_t)s4.w * 128 + lane * 4);
        red_add_v4(g_agg + (size_t)d4.x * 128 + lane * 4, v0);
        red_add_v4(g_agg + (size_t)d4.y * 128 + lane * 4, v1);
        red_add_v4(g_agg + (size_t)d4.z * 128 + lane * 4, v2);
        red_add_v4(g_agg + (size_t)d4.w * 128 + lane * 4, v3);
    } else {
        for (int e = e0; e < E; e++) {
            int src = __ldg(&ei[e]);
            int dst = __ldg(&ei[E + e]);
            float4 v = *(const float4*)(g_h1 + (size_t)src * 128 + lane * 4);
            red_add_v4(g_agg + (size_t)dst * 128 + lane * 4, v);
        }
    }
}

// ---------------------------------------------------------------------------
// GEMM2: h2[N,40] = relu(agg[N,128]) @ W2[128,40]
// 64-row tile, thread handles rows (r, r+32) x 5 cols via packed f32x2.
// ---------------------------------------------------------------------------
__global__ __launch_bounds__(256)
void gemm2_kernel(const float* __restrict__ W2, int N) {
    __shared__ float Ws[128 * 40];   // 20 KB
    __shared__ float As[64][129];    // ~33 KB, padded for conflict-free col reads

    const int t = threadIdx.x;
    const int row0 = blockIdx.x * 64;

    for (int i = t; i < 128 * 40; i += 256) Ws[i] = W2[i];

    #pragma unroll
    for (int i = 0; i < 8; i++) {
        int lin = t + i * 256;          // float4 index in [0,2048)
        int r   = lin >> 5;             // row in tile (0..63)
        int c4  = (lin & 31) << 2;      // col (float index)
        int grow = row0 + r;
        float4 v = make_float4(0.f, 0.f, 0.f, 0.f);
        if (grow < N) v = *(const float4*)(g_agg + (size_t)grow * 128 + c4);
        As[r][c4 + 0] = fmaxf(v.x, 0.f);
        As[r][c4 + 1] = fmaxf(v.y, 0.f);
        As[r][c4 + 2] = fmaxf(v.z, 0.f);
        As[r][c4 + 3] = fmaxf(v.w, 0.f);
    }
    __syncthreads();

    const int r     = t & 31;    // rows r and r+32
    const int cbase = t >> 5;    // 0..7; cols cbase + 8*i (warp-broadcast Ws)

    unsigned long long acc2[5] = {0ull, 0ull, 0ull, 0ull, 0ull};
    #pragma unroll 4
    for (int k = 0; k < 128; k++) {
        unsigned long long ap = pack2(As[r][k], As[r + 32][k]);
        #pragma unroll
        for (int i = 0; i < 5; i++) {
            float w = Ws[k * 40 + cbase + i * 8];
            fma2(acc2[i], ap, pack2(w, w));
        }
    }

    int g0 = row0 + r;
    int g1 = row0 + r + 32;
    #pragma unroll
    for (int i = 0; i < 5; i++) {
        float lo, hi;
        unpack2(acc2[i], lo, hi);
        if (g0 < N) g_h2[(size_t)g0 * 40 + cbase + i * 8] = lo;
        if (g1 < N) g_h2[(size_t)g1 * 40 + cbase + i * 8] = hi;
    }
}

// ---------------------------------------------------------------------------
// Scatter layer 2: out[dst] += h2[src] (width 40 = 10 float4).
// One thread per edge, 10 independent gathers + 10 vector reductions.
// ---------------------------------------------------------------------------
__global__ __launch_bounds__(256)
void scatter2_kernel(const int* __restrict__ ei, int E,
                     float* __restrict__ OUT) {
    int e = blockIdx.x * blockDim.x + threadIdx.x;
    if (e >= E) return;
    int src = __ldg(&ei[e]);
    int dst = __ldg(&ei[E + e]);
    const float* sp = g_h2 + (size_t)src * 40;
    float* dp = OUT + (size_t)dst * 40;
    float4 v[10];
    #pragma unroll
    for (int c = 0; c < 10; c++) v[c] = *(const float4*)(sp + c * 4);
    #pragma unroll
    for (int c = 0; c < 10; c++) red_add_v4(dp + c * 4, v[c]);
}

// ---------------------------------------------------------------------------
// launch
// ---------------------------------------------------------------------------
extern "C" void kernel_launch(void* const* d_in, const int* in_sizes, int n_in,
                              void* d_out, int out_size) {
    const float* x  = (const float*)d_in[0];
    const int*   ei = (const int*)d_in[1];     // int32 edge indices
    const float* W1 = (const float*)d_in[2];
    const float* W2 = (const float*)d_in[3];
    float* out = (float*)d_out;

    const int N = in_sizes[0] / 256;
    const int E = in_sizes[1] / 2;

    {
        int n4 = N_NODES * 128 / 4;
        zero_agg_kernel<<<(n4 + 255) / 256, 256>>>();
        int o4 = N * 40 / 4;
        zero_out_kernel<<<(o4 + 255) / 256, 256>>>((float4*)out, o4);
    }

    // layer 1: transform
    gemm1_kernel<<<(N + 63) / 64, 256>>>(x, W1, N);
    // layer 1: aggregate (4 edges per warp)
    {
        int warps = (E + 3) / 4;
        int blocks = (warps + 7) / 8;          // 8 warps per 256-thread block
        scatter1_kernel<<<blocks, 256>>>(ei, E);
    }
    // layer 2: relu + transform
    gemm2_kernel<<<(N + 63) / 64, 256>>>(W2, N);
    // layer 2: aggregate into output (thread per edge)
    scatter2_kernel<<<(E + 255) / 256, 256>>>(ei, E, out);
}

// round 6
// speedup vs baseline: 1.5360x; 1.3481x over previous
#include <cuda_runtime.h>
#include <cuda_bf16.h>
#include <stdint.h>

// ---------------------------------------------------------------------------
// GCN 2-layer, CSR-bucketed aggregation:
//   h1  = x @ W1                          [N,128]
//   agg = relu(csr_sum(h1[src] -> dst))   [N,128]   (atomic-free)
//   h2  = agg @ W2                        [N,40]
//   out = csr_sum(h2[src] -> dst)         [N,40]    (atomic-free)
// N = 100000, E = 1600000, x/W fp32, edge_index int32.
// ---------------------------------------------------------------------------

#define NN       100000
#define NE       1600000
#define SCHUNK   2048
#define NCHUNK   ((NN + SCHUNK - 1) / SCHUNK)   // 49

__device__ float g_h1[NN * 128];    // 51.2 MB
__device__ float g_agg[NN * 128];   // 51.2 MB
__device__ float g_h2[NN * 40];     // 16.0 MB
__device__ int   g_cnt[NN];
__device__ int   g_off[NN + 1];
__device__ int   g_cur[NN];
__device__ int   g_part[NCHUNK];
__device__ int   g_srt[NE];         // src indices sorted by dst

// ---------------------------------------------------------------------------
// packed f32x2 helpers (sm_103a dual fp32 FMA)
// ---------------------------------------------------------------------------
__device__ __forceinline__ unsigned long long pack2(float x, float y) {
    unsigned long long r;
    asm("mov.b64 %0, {%1, %2};" : "=l"(r) : "f"(x), "f"(y));
    return r;
}
__device__ __forceinline__ void unpack2(unsigned long long p, float& x, float& y) {
    asm("mov.b64 {%0, %1}, %2;" : "=f"(x), "=f"(y) : "l"(p));
}
__device__ __forceinline__ void fma2(unsigned long long& c,
                                     unsigned long long a,
                                     unsigned long long b) {
    asm("fma.rn.f32x2 %0, %1, %2, %0;" : "+l"(c) : "l"(a), "l"(b));
}

// ---------------------------------------------------------------------------
// CSR build: zero counts -> histogram(dst) -> scan -> bucket scatter
// ---------------------------------------------------------------------------
__global__ void zero_cnt_kernel() {
    int i = blockIdx.x * blockDim.x + threadIdx.x;
    if (i < NN) g_cnt[i] = 0;
}

__global__ void hist_kernel(const int* __restrict__ ei, int E) {
    int e = blockIdx.x * blockDim.x + threadIdx.x;
    if (e < E) atomicAdd(&g_cnt[__ldg(&ei[E + e])], 1);
}

__global__ void scan1_kernel() {
    __shared__ int sm[256];
    int base = blockIdx.x * SCHUNK + threadIdx.x * 8;
    int s = 0;
    #pragma unroll
    for (int i = 0; i < 8; i++) {
        int idx = base + i;
        if (idx < NN) s += g_cnt[idx];
    }
    sm[threadIdx.x] = s;
    __syncthreads();
    for (int o = 128; o > 0; o >>= 1) {
        if (threadIdx.x < o) sm[threadIdx.x] += sm[threadIdx.x + o];
        __syncthreads();
    }
    if (threadIdx.x == 0) g_part[blockIdx.x] = sm[0];
}

__global__ void scan2_kernel(int E) {
    if (threadIdx.x == 0) {
        int acc = 0;
        for (int i = 0; i < NCHUNK; i++) {
            int v = g_part[i];
            g_part[i] = acc;
            acc += v;
        }
        g_off[NN] = E;
    }
}

__global__ void scan3_kernel() {
    __shared__ int sm[256];
    const int t = threadIdx.x;
    int base = blockIdx.x * SCHUNK + t * 8;
    int v[8];
    int s = 0;
    #pragma unroll
    for (int i = 0; i < 8; i++) {
        int idx = base + i;
        v[i] = (idx < NN) ? g_cnt[idx] : 0;
        s += v[i];
    }
    sm[t] = s;
    __syncthreads();
    for (int o = 1; o < 256; o <<= 1) {          // inclusive Hillis-Steele
        int x = (t >= o) ? sm[t - o] : 0;
        __syncthreads();
        sm[t] += x;
        __syncthreads();
    }
    int run = sm[t] - s + g_part[blockIdx.x];     // exclusive prefix for thread
    #pragma unroll
    for (int i = 0; i < 8; i++) {
        int idx = base + i;
        if (idx < NN) { g_off[idx] = run; g_cur[idx] = run; }
        run += v[i];
    }
}

__global__ void build_kernel(const int* __restrict__ ei, int E) {
    int e = blockIdx.x * blockDim.x + threadIdx.x;
    if (e < E) {
        int d = __ldg(&ei[E + e]);
        int pos = atomicAdd(&g_cur[d], 1);
        g_srt[pos] = __ldg(&ei[e]);
    }
}

// ---------------------------------------------------------------------------
// GEMM1: h1[N,128] = x[N,256] @ W1[256,128]
// BM=64, BN=128, BK=16, 256 threads, 8x4 micro-tile, packed f32x2 FMAs.
// ---------------------------------------------------------------------------
__global__ __launch_bounds__(256, 4)
void gemm1_kernel(const float* __restrict__ X, const float* __restrict__ W, int N) {
    __shared__ float At[16][68];    // [k][row], padded
    __shared__ float Bs[16][128];

    const int tid = threadIdx.x;
    const int tx  = tid & 31;
    const int ty  = tid >> 5;
    const int block_row = blockIdx.x * 64;

    const int arow = tid >> 2;
    const int acol = (tid & 3) << 2;
    const int brow = tid >> 4;
    const int bcol = (tid & 15) << 3;

    unsigned long long acc2[8][2];
    #pragma unroll
    for (int i = 0; i < 8; i++) { acc2[i][0] = 0ull; acc2[i][1] = 0ull; }

    for (int k0 = 0; k0 < 256; k0 += 16) {
        int grow = block_row + arow;
        float4 av = make_float4(0.f, 0.f, 0.f, 0.f);
        if (grow < N) av = *(const float4*)(X + (size_t)grow * 256 + k0 + acol);
        At[acol + 0][arow] = av.x;
        At[acol + 1][arow] = av.y;
        At[acol + 2][arow] = av.z;
        At[acol + 3][arow] = av.w;
        const float* wb = W + (size_t)(k0 + brow) * 128 + bcol;
        *(float4*)&Bs[brow][bcol]     = *(const float4*)(wb);
        *(float4*)&Bs[brow][bcol + 4] = *(const float4*)(wb + 4);
        __syncthreads();

        #pragma unroll
        for (int k = 0; k < 16; k++) {
            float4 a0 = *(const float4*)&At[k][ty * 8];
            float4 a1 = *(const float4*)&At[k][ty * 8 + 4];
            float4 b  = *(const float4*)&Bs[k][tx * 4];
            unsigned long long b01 = pack2(b.x, b.y);
            unsigned long long b23 = pack2(b.z, b.w);
            float a[8] = {a0.x, a0.y, a0.z, a0.w, a1.x, a1.y, a1.z, a1.w};
            #pragma unroll
            for (int i = 0; i < 8; i++) {
                unsigned long long ap = pack2(a[i], a[i]);
                fma2(acc2[i][0], ap, b01);
                fma2(acc2[i][1], ap, b23);
            }
        }
        __syncthreads();
    }

    #pragma unroll
    for (int i = 0; i < 8; i++) {
        int grow = block_row + ty * 8 + i;
        if (grow < N) {
            float4 v;
            unpack2(acc2[i][0], v.x, v.y);
            unpack2(acc2[i][1], v.z, v.w);
            *(float4*)(g_h1 + (size_t)grow * 128 + tx * 4) = v;
        }
    }
}

// ---------------------------------------------------------------------------
// CSR aggregate layer 1 + relu: agg[n] = relu(sum_{e in bucket(n)} h1[srt[e]])
// Warp per node; 4-edge software pipeline for MLP; one sequential row write.
// ---------------------------------------------------------------------------
__global__ __launch_bounds__(256)
void agg1_kernel() {
    int node = blockIdx.x * 8 + (threadIdx.x >> 5);
    if (node >= NN) return;
    const int lane = threadIdx.x & 31;
    int beg = __ldg(&g_off[node]);
    int end = __ldg(&g_off[node + 1]);

    float4 acc = make_float4(0.f, 0.f, 0.f, 0.f);
    int e = beg;
    for (; e + 4 <= end; e += 4) {
        int s0 = __ldg(&g_srt[e + 0]);
        int s1 = __ldg(&g_srt[e + 1]);
        int s2 = __ldg(&g_srt[e + 2]);
        int s3 = __ldg(&g_srt[e + 3]);
        float4 v0 = *(const float4*)(g_h1 + (size_t)s0 * 128 + lane * 4);
        float4 v1 = *(const float4*)(g_h1 + (size_t)s1 * 128 + lane * 4);
        float4 v2 = *(const float4*)(g_h1 + (size_t)s2 * 128 + lane * 4);
        float4 v3 = *(const float4*)(g_h1 + (size_t)s3 * 128 + lane * 4);
        acc.x += (v0.x + v1.x) + (v2.x + v3.x);
        acc.y += (v0.y + v1.y) + (v2.y + v3.y);
        acc.z += (v0.z + v1.z) + (v2.z + v3.z);
        acc.w += (v0.w + v1.w) + (v2.w + v3.w);
    }
    for (; e < end; e++) {
        int s = __ldg(&g_srt[e]);
        float4 v = *(const float4*)(g_h1 + (size_t)s * 128 + lane * 4);
        acc.x += v.x; acc.y += v.y; acc.z += v.z; acc.w += v.w;
    }
    acc.x = fmaxf(acc.x, 0.f);
    acc.y = fmaxf(acc.y, 0.f);
    acc.z = fmaxf(acc.z, 0.f);
    acc.w = fmaxf(acc.w, 0.f);
    *(float4*)(g_agg + (size_t)node * 128 + lane * 4) = acc;
}

// ---------------------------------------------------------------------------
// GEMM2: h2[N,40] = agg[N,128] @ W2[128,40]   (agg already relu'd; fmax kept,
// relu is idempotent). 64-row tile, row-pair f32x2 blocking.
// ---------------------------------------------------------------------------
__global__ __launch_bounds__(256)
void gemm2_kernel(const float* __restrict__ W2, int N) {
    __shared__ float Ws[128 * 40];   // 20 KB
    __shared__ float As[64][129];    // padded for conflict-free column reads

    const int t = threadIdx.x;
    const int row0 = blockIdx.x * 64;

    for (int i = t; i < 128 * 40; i += 256) Ws[i] = W2[i];

    #pragma unroll
    for (int i = 0; i < 8; i++) {
        int lin = t + i * 256;
        int r   = lin >> 5;
        int c4  = (lin & 31) << 2;
        int grow = row0 + r;
        float4 v = make_float4(0.f, 0.f, 0.f, 0.f);
        if (grow < N) v = *(const float4*)(g_agg + (size_t)grow * 128 + c4);
        As[r][c4 + 0] = v.x;
        As[r][c4 + 1] = v.y;
        As[r][c4 + 2] = v.z;
        As[r][c4 + 3] = v.w;
    }
    __syncthreads();

    const int r     = t & 31;
    const int cbase = t >> 5;

    unsigned long long acc2[5] = {0ull, 0ull, 0ull, 0ull, 0ull};
    #pragma unroll 4
    for (int k = 0; k < 128; k++) {
        unsigned long long ap = pack2(As[r][k], As[r + 32][k]);
        #pragma unroll
        for (int i = 0; i < 5; i++) {
            float w = Ws[k * 40 + cbase + i * 8];
            fma2(acc2[i], ap, pack2(w, w));
        }
    }

    int g0 = row0 + r;
    int g1 = row0 + r + 32;
    #pragma unroll
    for (int i = 0; i < 5; i++) {
        float lo, hi;
        unpack2(acc2[i], lo, hi);
        if (g0 < N) g_h2[(size_t)g0 * 40 + cbase + i * 8] = lo;
        if (g1 < N) g_h2[(size_t)g1 * 40 + cbase + i * 8] = hi;
    }
}

// ---------------------------------------------------------------------------
// CSR aggregate layer 2: out[n] = sum h2[srt[e]]  (width 40)
// Warp per node; lane covers elements lane and lane+32 (lanes 0-7 only).
// Writes cover every node, including degree-0 (zeros) -> no out pre-zeroing.
// ---------------------------------------------------------------------------
__global__ __launch_bounds__(256)
void agg2_kernel(float* __restrict__ OUT) {
    int node = blockIdx.x * 8 + (threadIdx.x >> 5);
    if (node >= NN) return;
    const int lane = threadIdx.x & 31;
    int beg = __ldg(&g_off[node]);
    int end = __ldg(&g_off[node + 1]);

    float a0 = 0.f, a1 = 0.f;
    int e = beg;
    for (; e + 4 <= end; e += 4) {
        int s0 = __ldg(&g_srt[e + 0]);
        int s1 = __ldg(&g_srt[e + 1]);
        int s2 = __ldg(&g_srt[e + 2]);
        int s3 = __ldg(&g_srt[e + 3]);
        const float* p0 = g_h2 + (size_t)s0 * 40;
        const float* p1 = g_h2 + (size_t)s1 * 40;
        const float* p2 = g_h2 + (size_t)s2 * 40;
        const float* p3 = g_h2 + (size_t)s3 * 40;
        a0 += (p0[lane] + p1[lane]) + (p2[lane] + p3[lane]);
        if (lane < 8)
            a1 += (p0[lane + 32] + p1[lane + 32]) + (p2[lane + 32] + p3[lane + 32]);
    }
    for (; e < end; e++) {
        const float* p = g_h2 + (size_t)__ldg(&g_srt[e]) * 40;
        a0 += p[lane];
        if (lane < 8) a1 += p[lane + 32];
    }
    OUT[(size_t)node * 40 + lane] = a0;
    if (lane < 8) OUT[(size_t)node * 40 + 32 + lane] = a1;
}

// ---------------------------------------------------------------------------
// launch
// ---------------------------------------------------------------------------
extern "C" void kernel_launch(void* const* d_in, const int* in_sizes, int n_in,
                              void* d_out, int out_size) {
    const float* x  = (const float*)d_in[0];
    const int*   ei = (const int*)d_in[1];     // int32 edge indices
    const float* W1 = (const float*)d_in[2];
    const float* W2 = (const float*)d_in[3];
    float* out = (float*)d_out;

    const int N = in_sizes[0] / 256;
    const int E = in_sizes[1] / 2;

    // CSR build
    zero_cnt_kernel<<<(NN + 255) / 256, 256>>>();
    hist_kernel<<<(E + 255) / 256, 256>>>(ei, E);
    scan1_kernel<<<NCHUNK, 256>>>();
    scan2_kernel<<<1, 32>>>(E);
    scan3_kernel<<<NCHUNK, 256>>>();
    build_kernel<<<(E + 255) / 256, 256>>>(ei, E);

    // layer 1
    gemm1_kernel<<<(N + 63) / 64, 256>>>(x, W1, N);
    agg1_kernel<<<(NN + 7) / 8, 256>>>();

    // layer 2
    gemm2_kernel<<<(N + 63) / 64, 256>>>(W2, N);
    agg2_kernel<<<(NN + 7) / 8, 256>>>(out);
}

// round 8
// speedup vs baseline: 1.8487x; 1.2036x over previous
#include <cuda_runtime.h>
#include <cuda_bf16.h>
#include <stdint.h>

// ---------------------------------------------------------------------------
// GCN 2-layer, CSR aggregation + mma.sync bf16-split GEMM1:
//   h1  = x @ W1                          [N,128]   (tensor cores, 3-term bf16)
//   agg = relu(csr_sum(h1[src] -> dst))   [N,128]
//   h2  = agg @ W2                        [N,40]
//   out = csr_sum(h2[src] -> dst)         [N,40]
// N = 100000, E = 1600000, x/W fp32, edge_index int32.
// NOTE: harness compiles PTX at .target sm_103 (no 'a'): tcgen05 is
// unavailable; mma.sync (sm_80+ PTX) is the tensor-core path that compiles.
// ---------------------------------------------------------------------------

#define NN       100000
#define NE       1600000
#define SCHUNK   2048
#define NCHUNK   ((NN + SCHUNK - 1) / SCHUNK)   // 49

__device__ float g_h1[NN * 128];    // 51.2 MB
__device__ float g_agg[NN * 128];   // 51.2 MB
__device__ float g_h2[NN * 40];     // 16.0 MB
__device__ int   g_cnt[NN];
__device__ int   g_off[NN + 1];
__device__ int   g_cur[NN];
__device__ int   g_part[NCHUNK];
__device__ int   g_srt[NE];         // src indices sorted by dst
// W1 split to bf16 hi/lo, n-major [n=128][k=256]
__device__ __align__(16) __nv_bfloat16 g_whi[128 * 256];
__device__ __align__(16) __nv_bfloat16 g_wlo[128 * 256];

// ---------------------------------------------------------------------------
// helpers
// ---------------------------------------------------------------------------
__device__ __forceinline__ unsigned long long pack2(float x, float y) {
    unsigned long long r;
    asm("mov.b64 %0, {%1, %2};" : "=l"(r) : "f"(x), "f"(y));
    return r;
}
__device__ __forceinline__ void unpack2(unsigned long long p, float& x, float& y) {
    asm("mov.b64 {%0, %1}, %2;" : "=f"(x), "=f"(y) : "l"(p));
}
__device__ __forceinline__ void fma2(unsigned long long& c,
                                     unsigned long long a,
                                     unsigned long long b) {
    asm("fma.rn.f32x2 %0, %1, %2, %0;" : "+l"(c) : "l"(a), "l"(b));
}
__device__ __forceinline__ unsigned int bf2pk(float a, float b) {
    __nv_bfloat162 t = __floats2bfloat162_rn(a, b);
    return *(unsigned int*)&t;
}
// D += A*B, m16n8k16, bf16 inputs, fp32 accum
__device__ __forceinline__ void mma16816(float* c, const uint32_t* a, const uint32_t* b) {
    asm volatile(
        "mma.sync.aligned.m16n8k16.row.col.f32.bf16.bf16.f32 "
        "{%0,%1,%2,%3}, {%4,%5,%6,%7}, {%8,%9}, {%0,%1,%2,%3};"
        : "+f"(c[0]), "+f"(c[1]), "+f"(c[2]), "+f"(c[3])
        : "r"(a[0]), "r"(a[1]), "r"(a[2]), "r"(a[3]), "r"(b[0]), "r"(b[1]));
}

// ---------------------------------------------------------------------------
// CSR build: zero counts -> histogram(dst) -> scan -> bucket scatter
// ---------------------------------------------------------------------------
__global__ void zero_cnt_kernel() {
    int i = blockIdx.x * blockDim.x + threadIdx.x;
    if (i < NN) g_cnt[i] = 0;
}

__global__ void hist_kernel(const int* __restrict__ ei, int E) {
    int e = blockIdx.x * blockDim.x + threadIdx.x;
    if (e < E) atomicAdd(&g_cnt[__ldg(&ei[E + e])], 1);
}

__global__ void scan1_kernel() {
    __shared__ int sm[256];
    int base = blockIdx.x * SCHUNK + threadIdx.x * 8;
    int s = 0;
    #pragma unroll
    for (int i = 0; i < 8; i++) {
        int idx = base + i;
        if (idx < NN) s += g_cnt[idx];
    }
    sm[threadIdx.x] = s;
    __syncthreads();
    for (int o = 128; o > 0; o >>= 1) {
        if (threadIdx.x < o) sm[threadIdx.x] += sm[threadIdx.x + o];
        __syncthreads();
    }
    if (threadIdx.x == 0) g_part[blockIdx.x] = sm[0];
}

__global__ void scan2_kernel(int E) {
    if (threadIdx.x == 0) {
        int acc = 0;
        for (int i = 0; i < NCHUNK; i++) {
            int v = g_part[i];
            g_part[i] = acc;
            acc += v;
        }
        g_off[NN] = E;
    }
}

__global__ void scan3_kernel() {
    __shared__ int sm[256];
    const int t = threadIdx.x;
    int base = blockIdx.x * SCHUNK + t * 8;
    int v[8];
    int s = 0;
    #pragma unroll
    for (int i = 0; i < 8; i++) {
        int idx = base + i;
        v[i] = (idx < NN) ? g_cnt[idx] : 0;
        s += v[i];
    }
    sm[t] = s;
    __syncthreads();
    for (int o = 1; o < 256; o <<= 1) {
        int x = (t >= o) ? sm[t - o] : 0;
        __syncthreads();
        sm[t] += x;
        __syncthreads();
    }
    int run = sm[t] - s + g_part[blockIdx.x];
    #pragma unroll
    for (int i = 0; i < 8; i++) {
        int idx = base + i;
        if (idx < NN) { g_off[idx] = run; g_cur[idx] = run; }
        run += v[i];
    }
}

__global__ void build_kernel(const int* __restrict__ ei, int E) {
    int e = blockIdx.x * blockDim.x + threadIdx.x;
    if (e < E) {
        int d = __ldg(&ei[E + e]);
        int pos = atomicAdd(&g_cur[d], 1);
        g_srt[pos] = __ldg(&ei[e]);
    }
}

// ---------------------------------------------------------------------------
// W1 prep: split fp32 -> bf16 hi/lo, n-major [n][k] for col-major B frags.
// ---------------------------------------------------------------------------
__global__ void wprep_kernel(const float* __restrict__ W1) {
    int i = blockIdx.x * blockDim.x + threadIdx.x;   // 0..32767
    if (i >= 256 * 128) return;
    int k = i >> 7, n = i & 127;                     // W1 row-major [k][n]
    float w = W1[i];
    __nv_bfloat16 hi = __float2bfloat16(w);
    __nv_bfloat16 lo = __float2bfloat16(w - __bfloat162float(hi));
    g_whi[n * 256 + k] = hi;
    g_wlo[n * 256 + k] = lo;
}

// ---------------------------------------------------------------------------
// GEMM1 via mma.sync: h1[N,128] = x[N,256] @ W1[256,128]
// CTA 128 rows x N=128, 256 threads (8 warps, 4m x 2n), warp tile 32x64.
// K in 4 chunks of 64. 3-term bf16 split shares one fp32 accumulator.
// SMEM tiles padded to 72 bf16/row (144B) for conflict-free frag loads.
// ---------------------------------------------------------------------------
#define G1_AHI  0
#define G1_ALO  18432
#define G1_BHI  36864
#define G1_BLO  55296
#define G1_SMEM 73728
#define G1_PITCH 144

__global__ __launch_bounds__(256)
void gemm1_mma_kernel(const float* __restrict__ X, int N) {
    extern __shared__ unsigned char smem[];
    unsigned char* pAhi = smem + G1_AHI;
    unsigned char* pAlo = smem + G1_ALO;
    unsigned char* pBhi = smem + G1_BHI;
    unsigned char* pBlo = smem + G1_BLO;

    const int tid  = threadIdx.x;
    const int wid  = tid >> 5;
    const int lane = tid & 31;
    const int wm   = wid & 3;        // 4 warps over M (32 rows each)
    const int wn   = wid >> 2;       // 2 warps over N (64 cols each)
    const int row0 = blockIdx.x * 128;

    float acc[2][8][4];
    #pragma unroll
    for (int mi = 0; mi < 2; mi++)
        #pragma unroll
        for (int ni = 0; ni < 8; ni++)
            #pragma unroll
            for (int j = 0; j < 4; j++) acc[mi][ni][j] = 0.f;

    const int ar  = tid >> 1;            // A-fill row (0..127)
    const int ach = (tid & 1) * 32;      // A-fill col base within chunk
    const int grow = row0 + ar;

    for (int kc = 0; kc < 4; kc++) {
        // ---- A tile fill: fp32 -> bf16 hi/lo
        {
            const float* xp = X + (size_t)grow * 256 + kc * 64 + ach;
            #pragma unroll
            for (int j = 0; j < 8; j++) {
                float4 f = make_float4(0.f, 0.f, 0.f, 0.f);
                if (grow < N) f = *(const float4*)(xp + j * 4);
                uint2 hv, lv;
                hv.x = bf2pk(f.x, f.y);
                hv.y = bf2pk(f.z, f.w);
                float rx = f.x - __bfloat162float(__float2bfloat16(f.x));
                float ry = f.y - __bfloat162float(__float2bfloat16(f.y));
                float rz = f.z - __bfloat162float(__float2bfloat16(f.z));
                float rw = f.w - __bfloat162float(__float2bfloat16(f.w));
                lv.x = bf2pk(rx, ry);
                lv.y = bf2pk(rz, rw);
                int boff = ar * G1_PITCH + (ach + j * 4) * 2;
                *(uint2*)(pAhi + boff) = hv;
                *(uint2*)(pAlo + boff) = lv;
            }
        }
        // ---- B tile fill: copy n-major bf16 chunk (L2-hot)
        {
            #pragma unroll
            for (int j = 0; j < 4; j++) {
                int lin = tid + j * 256;            // 0..1023
                int n   = lin >> 3;
                int k8  = (lin & 7) * 8;
                const unsigned char* sh = (const unsigned char*)g_whi + n * 512 + kc * 128 + k8 * 2;
                const unsigned char* sl = (const unsigned char*)g_wlo + n * 512 + kc * 128 + k8 * 2;
                int boff = n * G1_PITCH + k8 * 2;
                *(uint4*)(pBhi + boff) = *(const uint4*)sh;
                *(uint4*)(pBlo + boff) = *(const uint4*)sl;
            }
        }
        __syncthreads();

        // ---- compute: 4 k16 steps
        #pragma unroll
        for (int ks = 0; ks < 4; ks++) {
            const int cb = ks * 16 + (lane & 3) * 2;   // k element index
            uint32_t ahi[2][4], alo[2][4];
            #pragma unroll
            for (int mi = 0; mi < 2; mi++) {
                int r = wm * 32 + mi * 16 + (lane >> 2);
                ahi[mi][0] = *(const uint32_t*)(pAhi + r * G1_PITCH + cb * 2);
                ahi[mi][1] = *(const uint32_t*)(pAhi + (r + 8) * G1_PITCH + cb * 2);
                ahi[mi][2] = *(const uint32_t*)(pAhi + r * G1_PITCH + (cb + 8) * 2);
                ahi[mi][3] = *(const uint32_t*)(pAhi + (r + 8) * G1_PITCH + (cb + 8) * 2);
                alo[mi][0] = *(const uint32_t*)(pAlo + r * G1_PITCH + cb * 2);
                alo[mi][1] = *(const uint32_t*)(pAlo + (r + 8) * G1_PITCH + cb * 2);
                alo[mi][2] = *(const uint32_t*)(pAlo + r * G1_PITCH + (cb + 8) * 2);
                alo[mi][3] = *(const uint32_t*)(pAlo + (r + 8) * G1_PITCH + (cb + 8) * 2);
            }
            #pragma unroll
            for (int ni = 0; ni < 8; ni++) {
                int n = wn * 64 + ni * 8 + (lane >> 2);
                uint32_t bh[2], bl[2];
                bh[0] = *(const uint32_t*)(pBhi + n * G1_PITCH + cb * 2);
                bh[1] = *(const uint32_t*)(pBhi + n * G1_PITCH + (cb + 8) * 2);
                bl[0] = *(const uint32_t*)(pBlo + n * G1_PITCH + cb * 2);
                bl[1] = *(const uint32_t*)(pBlo + n * G1_PITCH + (cb + 8) * 2);
                #pragma unroll
                for (int mi = 0; mi < 2; mi++) {
                    mma16816(acc[mi][ni], ahi[mi], bh);   // hi*hi
                    mma16816(acc[mi][ni], alo[mi], bh);   // lo*hi
                    mma16816(acc[mi][ni], ahi[mi], bl);   // hi*lo
                }
            }
        }
        __syncthreads();
    }

    // ---- epilogue: write fp32 fragments
    const int rbase = row0 + wm * 32 + (lane >> 2);
    const int cbase = wn * 64 + (lane & 3) * 2;
    #pragma unroll
    for (int mi = 0; mi < 2; mi++) {
        #pragma unroll
        for (int ni = 0; ni < 8; ni++) {
            int r = rbase + mi * 16;
            int c = cbase + ni * 8;
            if (r < N)
                *(float2*)(g_h1 + (size_t)r * 128 + c) =
                    make_float2(acc[mi][ni][0], acc[mi][ni][1]);
            if (r + 8 < N)
                *(float2*)(g_h1 + (size_t)(r + 8) * 128 + c) =
                    make_float2(acc[mi][ni][2], acc[mi][ni][3]);
        }
    }
}

// ---------------------------------------------------------------------------
// CSR aggregate layer 1 + relu (warp per node, 4-edge pipeline)
// ---------------------------------------------------------------------------
__global__ __launch_bounds__(256)
void agg1_kernel() {
    int node = blockIdx.x * 8 + (threadIdx.x >> 5);
    if (node >= NN) return;
    const int lane = threadIdx.x & 31;
    int beg = __ldg(&g_off[node]);
    int end = __ldg(&g_off[node + 1]);

    float4 acc = make_float4(0.f, 0.f, 0.f, 0.f);
    int e = beg;
    for (; e + 4 <= end; e += 4) {
        int s0 = __ldg(&g_srt[e + 0]);
        int s1 = __ldg(&g_srt[e + 1]);
        int s2 = __ldg(&g_srt[e + 2]);
        int s3 = __ldg(&g_srt[e + 3]);
        float4 v0 = *(const float4*)(g_h1 + (size_t)s0 * 128 + lane * 4);
        float4 v1 = *(const float4*)(g_h1 + (size_t)s1 * 128 + lane * 4);
        float4 v2 = *(const float4*)(g_h1 + (size_t)s2 * 128 + lane * 4);
        float4 v3 = *(const float4*)(g_h1 + (size_t)s3 * 128 + lane * 4);
        acc.x += (v0.x + v1.x) + (v2.x + v3.x);
        acc.y += (v0.y + v1.y) + (v2.y + v3.y);
        acc.z += (v0.z + v1.z) + (v2.z + v3.z);
        acc.w += (v0.w + v1.w) + (v2.w + v3.w);
    }
    for (; e < end; e++) {
        int s = __ldg(&g_srt[e]);
        float4 v = *(const float4*)(g_h1 + (size_t)s * 128 + lane * 4);
        acc.x += v.x; acc.y += v.y; acc.z += v.z; acc.w += v.w;
    }
    acc.x = fmaxf(acc.x, 0.f);
    acc.y = fmaxf(acc.y, 0.f);
    acc.z = fmaxf(acc.z, 0.f);
    acc.w = fmaxf(acc.w, 0.f);
    *(float4*)(g_agg + (size_t)node * 128 + lane * 4) = acc;
}

// ---------------------------------------------------------------------------
// GEMM2: h2[N,40] = agg[N,128] @ W2[128,40]  (f32x2, row-pair blocking)
// ---------------------------------------------------------------------------
__global__ __launch_bounds__(256)
void gemm2_kernel(const float* __restrict__ W2, int N) {
    __shared__ float Ws[128 * 40];
    __shared__ float As[64][129];

    const int t = threadIdx.x;
    const int row0 = blockIdx.x * 64;

    for (int i = t; i < 128 * 40; i += 256) Ws[i] = W2[i];

    #pragma unroll
    for (int i = 0; i < 8; i++) {
        int lin = t + i * 256;
        int r   = lin >> 5;
        int c4  = (lin & 31) << 2;
        int grow = row0 + r;
        float4 v = make_float4(0.f, 0.f, 0.f, 0.f);
        if (grow < N) v = *(const float4*)(g_agg + (size_t)grow * 128 + c4);
        As[r][c4 + 0] = v.x;
        As[r][c4 + 1] = v.y;
        As[r][c4 + 2] = v.z;
        As[r][c4 + 3] = v.w;
    }
    __syncthreads();

    const int r     = t & 31;
    const int cbase = t >> 5;

    unsigned long long acc2[5] = {0ull, 0ull, 0ull, 0ull, 0ull};
    #pragma unroll 4
    for (int k = 0; k < 128; k++) {
        unsigned long long ap = pack2(As[r][k], As[r + 32][k]);
        #pragma unroll
        for (int i = 0; i < 5; i++) {
            float w = Ws[k * 40 + cbase + i * 8];
            fma2(acc2[i], ap, pack2(w, w));
        }
    }

    int g0 = row0 + r;
    int g1 = row0 + r + 32;
    #pragma unroll
    for (int i = 0; i < 5; i++) {
        float lo, hi;
        unpack2(acc2[i], lo, hi);
        if (g0 < N) g_h2[(size_t)g0 * 40 + cbase + i * 8] = lo;
        if (g1 < N) g_h2[(size_t)g1 * 40 + cbase + i * 8] = hi;
    }
}

// ---------------------------------------------------------------------------
// CSR aggregate layer 2 (warp per node, width 40)
// ---------------------------------------------------------------------------
__global__ __launch_bounds__(256)
void agg2_kernel(float* __restrict__ OUT) {
    int node = blockIdx.x * 8 + (threadIdx.x >> 5);
    if (node >= NN) return;
    const int lane = threadIdx.x & 31;
    int beg = __ldg(&g_off[node]);
    int end = __ldg(&g_off[node + 1]);

    float a0 = 0.f, a1 = 0.f;
    int e = beg;
    for (; e + 4 <= end; e += 4) {
        int s0 = __ldg(&g_srt[e + 0]);
        int s1 = __ldg(&g_srt[e + 1]);
        int s2 = __ldg(&g_srt[e + 2]);
        int s3 = __ldg(&g_srt[e + 3]);
        const float* p0 = g_h2 + (size_t)s0 * 40;
        const float* p1 = g_h2 + (size_t)s1 * 40;
        const float* p2 = g_h2 + (size_t)s2 * 40;
        const float* p3 = g_h2 + (size_t)s3 * 40;
        a0 += (p0[lane] + p1[lane]) + (p2[lane] + p3[lane]);
        if (lane < 8)
            a1 += (p0[lane + 32] + p1[lane + 32]) + (p2[lane + 32] + p3[lane + 32]);
    }
    for (; e < end; e++) {
        const float* p = g_h2 + (size_t)__ldg(&g_srt[e]) * 40;
        a0 += p[lane];
        if (lane < 8) a1 += p[lane + 32];
    }
    OUT[(size_t)node * 40 + lane] = a0;
    if (lane < 8) OUT[(size_t)node * 40 + 32 + lane] = a1;
}

// ---------------------------------------------------------------------------
// launch
// ---------------------------------------------------------------------------
extern "C" void kernel_launch(void* const* d_in, const int* in_sizes, int n_in,
                              void* d_out, int out_size) {
    const float* x  = (const float*)d_in[0];
    const int*   ei = (const int*)d_in[1];     // int32 edge indices
    const float* W1 = (const float*)d_in[2];
    const float* W2 = (const float*)d_in[3];
    float* out = (float*)d_out;

    const int N = in_sizes[0] / 256;
    const int E = in_sizes[1] / 2;

    cudaFuncSetAttribute(gemm1_mma_kernel,
                         cudaFuncAttributeMaxDynamicSharedMemorySize, G1_SMEM);

    // CSR build
    zero_cnt_kernel<<<(NN + 255) / 256, 256>>>();
    hist_kernel<<<(E + 255) / 256, 256>>>(ei, E);
    scan1_kernel<<<NCHUNK, 256>>>();
    scan2_kernel<<<1, 32>>>(E);
    scan3_kernel<<<NCHUNK, 256>>>();
    build_kernel<<<(E + 255) / 256, 256>>>(ei, E);

    // layer 1
    wprep_kernel<<<128, 256>>>(W1);
    gemm1_mma_kernel<<<(N + 127) / 128, 256, G1_SMEM>>>(x, N);
    agg1_kernel<<<(NN + 7) / 8, 256>>>();

    // layer 2
    gemm2_kernel<<<(N + 63) / 64, 256>>>(W2, N);
    agg2_kernel<<<(NN + 7) / 8, 256>>>(out);
}

// round 10
// speedup vs baseline: 1.9524x; 1.0561x over previous
#include <cuda_runtime.h>
#include <cuda_bf16.h>
#include <cuda_fp16.h>
#include <stdint.h>

// ---------------------------------------------------------------------------
// GCN 2-layer, CSR aggregation + mma.sync bf16-split GEMM1 (ldmatrix frags):
//   h1  = x @ W1                          [N,128]   (tensor cores, fp16 store)
//   agg = relu(csr_sum(h1[src] -> dst))   [N,128]   (fp32 accum)
//   h2  = agg @ W2                        [N,40]
//   out = csr_sum(h2[src] -> dst)         [N,40]
// N = 100000, E = 1600000, x/W fp32, edge_index int32.
// ---------------------------------------------------------------------------

#define NN       100000
#define NE       1600000
#define SCHUNK   2048
#define NCHUNK   ((NN + SCHUNK - 1) / SCHUNK)   // 49

__device__ __half g_h1h[NN * 128];  // 25.6 MB (fp16 h1)
__device__ float g_agg[NN * 128];   // 51.2 MB
__device__ float g_h2[NN * 40];     // 16.0 MB
__device__ int   g_cnt[NN];
__device__ int   g_off[NN + 1];
__device__ int   g_cur[NN];
__device__ int   g_part[NCHUNK];
__device__ int   g_srt[NE];         // src indices sorted by dst
// W1 split to bf16 hi/lo, n-major [n=128][k=256]
__device__ __align__(16) __nv_bfloat16 g_whi[128 * 256];
__device__ __align__(16) __nv_bfloat16 g_wlo[128 * 256];

// ---------------------------------------------------------------------------
// helpers
// ---------------------------------------------------------------------------
__device__ __forceinline__ uint32_t smem_u32(const void* p) {
    uint32_t a;
    asm("{ .reg .u64 t; cvta.to.shared.u64 t, %1; cvt.u32.u64 %0, t; }"
        : "=r"(a) : "l"(p));
    return a;
}
__device__ __forceinline__ unsigned long long pack2(float x, float y) {
    unsigned long long r;
    asm("mov.b64 %0, {%1, %2};" : "=l"(r) : "f"(x), "f"(y));
    return r;
}
__device__ __forceinline__ void unpack2(unsigned long long p, float& x, float& y) {
    asm("mov.b64 {%0, %1}, %2;" : "=f"(x), "=f"(y) : "l"(p));
}
__device__ __forceinline__ void fma2(unsigned long long& c,
                                     unsigned long long a,
                                     unsigned long long b) {
    asm("fma.rn.f32x2 %0, %1, %2, %0;" : "+l"(c) : "l"(a), "l"(b));
}
__device__ __forceinline__ unsigned int bf2pk(float a, float b) {
    __nv_bfloat162 t = __floats2bfloat162_rn(a, b);
    return *(unsigned int*)&t;
}
// D += A*B, m16n8k16, bf16 inputs, fp32 accum
__device__ __forceinline__ void mma16816(float* c, const uint32_t* a, const uint32_t* b) {
    asm volatile(
        "mma.sync.aligned.m16n8k16.row.col.f32.bf16.bf16.f32 "
        "{%0,%1,%2,%3}, {%4,%5,%6,%7}, {%8,%9}, {%0,%1,%2,%3};"
        : "+f"(c[0]), "+f"(c[1]), "+f"(c[2]), "+f"(c[3])
        : "r"(a[0]), "r"(a[1]), "r"(a[2]), "r"(a[3]), "r"(b[0]), "r"(b[1]));
}
__device__ __forceinline__ void ldsm4(uint32_t& r0, uint32_t& r1,
                                      uint32_t& r2, uint32_t& r3, uint32_t addr) {
    asm volatile("ldmatrix.sync.aligned.m8n8.x4.shared.b16 {%0,%1,%2,%3}, [%4];"
                 : "=r"(r0), "=r"(r1), "=r"(r2), "=r"(r3) : "r"(addr));
}

// ---------------------------------------------------------------------------
// CSR build: zero counts -> histogram(dst) -> scan -> bucket scatter
// ---------------------------------------------------------------------------
__global__ void zero_cnt_kernel() {
    int i = blockIdx.x * blockDim.x + threadIdx.x;
    if (i < NN) g_cnt[i] = 0;
}

__global__ void hist_kernel(const int* __restrict__ ei, int E) {
    int e = blockIdx.x * blockDim.x + threadIdx.x;
    if (e < E) atomicAdd(&g_cnt[__ldg(&ei[E + e])], 1);
}

__global__ void scan1_kernel() {
    __shared__ int sm[256];
    int base = blockIdx.x * SCHUNK + threadIdx.x * 8;
    int s = 0;
    #pragma unroll
    for (int i = 0; i < 8; i++) {
        int idx = base + i;
        if (idx < NN) s += g_cnt[idx];
    }
    sm[threadIdx.x] = s;
    __syncthreads();
    for (int o = 128; o > 0; o >>= 1) {
        if (threadIdx.x < o) sm[threadIdx.x] += sm[threadIdx.x + o];
        __syncthreads();
    }
    if (threadIdx.x == 0) g_part[blockIdx.x] = sm[0];
}

__global__ void scan2_kernel(int E) {
    if (threadIdx.x == 0) {
        int acc = 0;
        for (int i = 0; i < NCHUNK; i++) {
            int v = g_part[i];
            g_part[i] = acc;
            acc += v;
        }
        g_off[NN] = E;
    }
}

__global__ void scan3_kernel() {
    __shared__ int sm[256];
    const int t = threadIdx.x;
    int base = blockIdx.x * SCHUNK + t * 8;
    int v[8];
    int s = 0;
    #pragma unroll
    for (int i = 0; i < 8; i++) {
        int idx = base + i;
        v[i] = (idx < NN) ? g_cnt[idx] : 0;
        s += v[i];
    }
    sm[t] = s;
    __syncthreads();
    for (int o = 1; o < 256; o <<= 1) {
        int x = (t >= o) ? sm[t - o] : 0;
        __syncthreads();
        sm[t] += x;
        __syncthreads();
    }
    int run = sm[t] - s + g_part[blockIdx.x];
    #pragma unroll
    for (int i = 0; i < 8; i++) {
        int idx = base + i;
        if (idx < NN) { g_off[idx] = run; g_cur[idx] = run; }
        run += v[i];
    }
}

__global__ void build_kernel(const int* __restrict__ ei, int E) {
    int e = blockIdx.x * blockDim.x + threadIdx.x;
    if (e < E) {
        int d = __ldg(&ei[E + e]);
        int pos = atomicAdd(&g_cur[d], 1);
        g_srt[pos] = __ldg(&ei[e]);
    }
}

// ---------------------------------------------------------------------------
// W1 prep: split fp32 -> bf16 hi/lo, n-major [n][k] for col-major B frags.
// ---------------------------------------------------------------------------
__global__ void wprep_kernel(const float* __restrict__ W1) {
    int i = blockIdx.x * blockDim.x + threadIdx.x;   // 0..32767
    if (i >= 256 * 128) return;
    int k = i >> 7, n = i & 127;                     // W1 row-major [k][n]
    float w = W1[i];
    __nv_bfloat16 hi = __float2bfloat16(w);
    __nv_bfloat16 lo = __float2bfloat16(w - __bfloat162float(hi));
    g_whi[n * 256 + k] = hi;
    g_wlo[n * 256 + k] = lo;
}

// ---------------------------------------------------------------------------
// GEMM1 via mma.sync + ldmatrix: h1[N,128] = x[N,256] @ W1[256,128]
// CTA 128 rows x N=128, 256 threads (8 warps, 4m x 2n), warp tile 32x64.
// K in 4 chunks of 64. 3-term bf16 split (hi*hi + lo*hi + hi*lo).
// SMEM pitch 144B: ldmatrix rows land on distinct 16B bank groups.
// Epilogue writes h1 as fp16 (half2 pairs).
// ---------------------------------------------------------------------------
#define G1_AHI  0
#define G1_ALO  18432
#define G1_BHI  36864
#define G1_BLO  55296
#define G1_SMEM 73728
#define G1_PITCH 144

__global__ __launch_bounds__(256)
void gemm1_mma_kernel(const float* __restrict__ X, int N) {
    extern __shared__ unsigned char smem[];
    unsigned char* pAhi = smem + G1_AHI;
    unsigned char* pAlo = smem + G1_ALO;
    const uint32_t sb = smem_u32(smem);
    const uint32_t uAhi = sb + G1_AHI;
    const uint32_t uAlo = sb + G1_ALO;
    const uint32_t uBhi = sb + G1_BHI;
    const uint32_t uBlo = sb + G1_BLO;

    const int tid  = threadIdx.x;
    const int wid  = tid >> 5;
    const int lane = tid & 31;
    const int wm   = wid & 3;        // 4 warps over M (32 rows each)
    const int wn   = wid >> 2;       // 2 warps over N (64 cols each)
    const int row0 = blockIdx.x * 128;

    float acc[2][8][4];
    #pragma unroll
    for (int mi = 0; mi < 2; mi++)
        #pragma unroll
        for (int ni = 0; ni < 8; ni++)
            #pragma unroll
            for (int j = 0; j < 4; j++) acc[mi][ni][j] = 0.f;

    // ldmatrix per-lane base offsets
    // A (per mi): lanes 0-7 tile(r,cb), 8-15 (r+8,cb), 16-23 (r,cb+8), 24-31 (r+8,cb+8)
    uint32_t aoff[2];
    #pragma unroll
    for (int mi = 0; mi < 2; mi++) {
        int r = wm * 32 + mi * 16 + (lane & 7) + ((lane & 8) ? 8 : 0);
        aoff[mi] = r * G1_PITCH + ((lane & 16) ? 16 : 0);
    }
    // B (per ni-pair p): lanes 0-7 (n0..7,cb), 8-15 (n0..7,cb+8),
    //                    16-23 (n0+8..15,cb), 24-31 (n0+8..15,cb+8)
    uint32_t boff[4];
    #pragma unroll
    for (int p = 0; p < 4; p++) {
        int n = wn * 64 + p * 16 + (lane & 7) + ((lane & 16) ? 8 : 0);
        boff[p] = n * G1_PITCH + ((lane & 8) ? 16 : 0);
    }

    const int ar  = tid >> 1;            // A-fill row (0..127)
    const int ach = (tid & 1) * 32;      // A-fill col base within chunk
    const int grow = row0 + ar;

    for (int kc = 0; kc < 4; kc++) {
        // ---- A tile fill: fp32 -> bf16 hi/lo
        {
            const float* xp = X + (size_t)grow * 256 + kc * 64 + ach;
            #pragma unroll
            for (int j = 0; j < 8; j++) {
                float4 f = make_float4(0.f, 0.f, 0.f, 0.f);
                if (grow < N) f = *(const float4*)(xp + j * 4);
                uint2 hv, lv;
                hv.x = bf2pk(f.x, f.y);
                hv.y = bf2pk(f.z, f.w);
                float rx = f.x - __bfloat162float(__float2bfloat16(f.x));
                float ry = f.y - __bfloat162float(__float2bfloat16(f.y));
                float rz = f.z - __bfloat162float(__float2bfloat16(f.z));
                float rw = f.w - __bfloat162float(__float2bfloat16(f.w));
                lv.x = bf2pk(rx, ry);
                lv.y = bf2pk(rz, rw);
                int bo = ar * G1_PITCH + (ach + j * 4) * 2;
                *(uint2*)(pAhi + bo) = hv;
                *(uint2*)(pAlo + bo) = lv;
            }
        }
        // ---- B tile fill: copy n-major bf16 chunk (L2-hot)
        {
            #pragma unroll
            for (int j = 0; j < 4; j++) {
                int lin = tid + j * 256;            // 0..1023
                int n   = lin >> 3;
                int k8  = (lin & 7) * 8;
                const unsigned char* sh = (const unsigned char*)g_whi + n * 512 + kc * 128 + k8 * 2;
                const unsigned char* sl = (const unsigned char*)g_wlo + n * 512 + kc * 128 + k8 * 2;
                int bo = n * G1_PITCH + k8 * 2;
                *(uint4*)(smem + G1_BHI + bo) = *(const uint4*)sh;
                *(uint4*)(smem + G1_BLO + bo) = *(const uint4*)sl;
            }
        }
        __syncthreads();

        // ---- compute: 4 k16 steps
        #pragma unroll
        for (int ks = 0; ks < 4; ks++) {
            const uint32_t kb = ks * 32;
            uint32_t ahi[2][4], alo[2][4];
            #pragma unroll
            for (int mi = 0; mi < 2; mi++) {
                ldsm4(ahi[mi][0], ahi[mi][1], ahi[mi][2], ahi[mi][3], uAhi + aoff[mi] + kb);
                ldsm4(alo[mi][0], alo[mi][1], alo[mi][2], alo[mi][3], uAlo + aoff[mi] + kb);
            }
            #pragma unroll
            for (int p = 0; p < 4; p++) {
                uint32_t bh[4], bl[4];
                ldsm4(bh[0], bh[1], bh[2], bh[3], uBhi + boff[p] + kb);
                ldsm4(bl[0], bl[1], bl[2], bl[3], uBlo + boff[p] + kb);
                #pragma unroll
                for (int mi = 0; mi < 2; mi++) {
                    mma16816(acc[mi][2 * p],     ahi[mi], bh);      // hi*hi
                    mma16816(acc[mi][2 * p],     alo[mi], bh);      // lo*hi
                    mma16816(acc[mi][2 * p],     ahi[mi], bl);      // hi*lo
                    mma16816(acc[mi][2 * p + 1], ahi[mi], bh + 2);
                    mma16816(acc[mi][2 * p + 1], alo[mi], bh + 2);
                    mma16816(acc[mi][2 * p + 1], ahi[mi], bl + 2);
                }
            }
        }
        __syncthreads();
    }

    // ---- epilogue: write h1 as fp16 (half2 per 2 cols)
    const int rbase = row0 + wm * 32 + (lane >> 2);
    const int cbase = wn * 64 + (lane & 3) * 2;
    #pragma unroll
    for (int mi = 0; mi < 2; mi++) {
        #pragma unroll
        for (int ni = 0; ni < 8; ni++) {
            int r = rbase + mi * 16;
            int c = cbase + ni * 8;
            if (r < N) {
                __half2 h = __floats2half2_rn(acc[mi][ni][0], acc[mi][ni][1]);
                *(uint32_t*)(g_h1h + (size_t)r * 128 + c) = *(uint32_t*)&h;
            }
            if (r + 8 < N) {
                __half2 h = __floats2half2_rn(acc[mi][ni][2], acc[mi][ni][3]);
                *(uint32_t*)(g_h1h + (size_t)(r + 8) * 128 + c) = *(uint32_t*)&h;
            }
        }
    }
}

// ---------------------------------------------------------------------------
// CSR aggregate layer 1 + relu (warp per node, 4-edge pipeline, fp16 gather,
// fp32 accumulate). Lane handles 4 features = one uint2 (2 half2).
// ---------------------------------------------------------------------------
__global__ __launch_bounds__(256)
void agg1_kernel() {
    int node = blockIdx.x * 8 + (threadIdx.x >> 5);
    if (node >= NN) return;
    const int lane = threadIdx.x & 31;
    int beg = __ldg(&g_off[node]);
    int end = __ldg(&g_off[node + 1]);

    float4 acc = make_float4(0.f, 0.f, 0.f, 0.f);
    int e = beg;
    for (; e + 4 <= end; e += 4) {
        int s0 = __ldg(&g_srt[e + 0]);
        int s1 = __ldg(&g_srt[e + 1]);
        int s2 = __ldg(&g_srt[e + 2]);
        int s3 = __ldg(&g_srt[e + 3]);
        uint2 u0 = *(const uint2*)(g_h1h + (size_t)s0 * 128 + lane * 4);
        uint2 u1 = *(const uint2*)(g_h1h + (size_t)s1 * 128 + lane * 4);
        uint2 u2 = *(const uint2*)(g_h1h + (size_t)s2 * 128 + lane * 4);
        uint2 u3 = *(const uint2*)(g_h1h + (size_t)s3 * 128 + lane * 4);
        float2 a0 = __half22float2(*(__half2*)&u0.x), b0 = __half22float2(*(__half2*)&u0.y);
        float2 a1 = __half22float2(*(__half2*)&u1.x), b1 = __half22float2(*(__half2*)&u1.y);
        float2 a2 = __half22float2(*(__half2*)&u2.x), b2 = __half22float2(*(__half2*)&u2.y);
        float2 a3 = __half22float2(*(__half2*)&u3.x), b3 = __half22float2(*(__half2*)&u3.y);
        acc.x += (a0.x + a1.x) + (a2.x + a3.x);
        acc.y += (a0.y + a1.y) + (a2.y + a3.y);
        acc.z += (b0.x + b1.x) + (b2.x + b3.x);
        acc.w += (b0.y + b1.y) + (b2.y + b3.y);
    }
    for (; e < end; e++) {
        int s = __ldg(&g_srt[e]);
        uint2 u = *(const uint2*)(g_h1h + (size_t)s * 128 + lane * 4);
        float2 a = __half22float2(*(__half2*)&u.x), b = __half22float2(*(__half2*)&u.y);
        acc.x += a.x; acc.y += a.y; acc.z += b.x; acc.w += b.y;
    }
    acc.x = fmaxf(acc.x, 0.f);
    acc.y = fmaxf(acc.y, 0.f);
    acc.z = fmaxf(acc.z, 0.f);
    acc.w = fmaxf(acc.w, 0.f);
    *(float4*)(g_agg + (size_t)node * 128 + lane * 4) = acc;
}

// ---------------------------------------------------------------------------
// GEMM2: h2[N,40] = agg[N,128] @ W2[128,40]  (f32x2, row-pair blocking)
// ---------------------------------------------------------------------------
__global__ __launch_bounds__(256)
void gemm2_kernel(const float* __restrict__ W2, int N) {
    __shared__ float Ws[128 * 40];
    __shared__ float As[64][129];

    const int t = threadIdx.x;
    const int row0 = blockIdx.x * 64;

    for (int i = t; i < 128 * 40; i += 256) Ws[i] = W2[i];

    #pragma unroll
    for (int i = 0; i < 8; i++) {
        int lin = t + i * 256;
        int r   = lin >> 5;
        int c4  = (lin & 31) << 2;
        int grow = row0 + r;
        float4 v = make_float4(0.f, 0.f, 0.f, 0.f);
        if (grow < N) v = *(const float4*)(g_agg + (size_t)grow * 128 + c4);
        As[r][c4 + 0] = v.x;
        As[r][c4 + 1] = v.y;
        As[r][c4 + 2] = v.z;
        As[r][c4 + 3] = v.w;
    }
    __syncthreads();

    const int r     = t & 31;
    const int cbase = t >> 5;

    unsigned long long acc2[5] = {0ull, 0ull, 0ull, 0ull, 0ull};
    #pragma unroll 4
    for (int k = 0; k < 128; k++) {
        unsigned long long ap = pack2(As[r][k], As[r + 32][k]);
        #pragma unroll
        for (int i = 0; i < 5; i++) {
            float w = Ws[k * 40 + cbase + i * 8];
            fma2(acc2[i], ap, pack2(w, w));
        }
    }

    int g0 = row0 + r;
    int g1 = row0 + r + 32;
    #pragma unroll
    for (int i = 0; i < 5; i++) {
        float lo, hi;
        unpack2(acc2[i], lo, hi);
        if (g0 < N) g_h2[(size_t)g0 * 40 + cbase + i * 8] = lo;
        if (g1 < N) g_h2[(size_t)g1 * 40 + cbase + i * 8] = hi;
    }
}

// ---------------------------------------------------------------------------
// CSR aggregate layer 2 (warp per node, width 40)
// ---------------------------------------------------------------------------
__global__ __launch_bounds__(256)
void agg2_kernel(float* __restrict__ OUT) {
    int node = blockIdx.x * 8 + (threadIdx.x >> 5);
    if (node >= NN) return;
    const int lane = threadIdx.x & 31;
    int beg = __ldg(&g_off[node]);
    int end = __ldg(&g_off[node + 1]);

    float a0 = 0.f, a1 = 0.f;
    int e = beg;
    for (; e + 4 <= end; e += 4) {
        int s0 = __ldg(&g_srt[e + 0]);
        int s1 = __ldg(&g_srt[e + 1]);
        int s2 = __ldg(&g_srt[e + 2]);
        int s3 = __ldg(&g_srt[e + 3]);
        const float* p0 = g_h2 + (size_t)s0 * 40;
        const float* p1 = g_h2 + (size_t)s1 * 40;
        const float* p2 = g_h2 + (size_t)s2 * 40;
        const float* p3 = g_h2 + (size_t)s3 * 40;
        a0 += (p0[lane] + p1[lane]) + (p2[lane] + p3[lane]);
        if (lane < 8)
            a1 += (p0[lane + 32] + p1[lane + 32]) + (p2[lane + 32] + p3[lane + 32]);
    }
    for (; e < end; e++) {
        const float* p = g_h2 + (size_t)__ldg(&g_srt[e]) * 40;
        a0 += p[lane];
        if (lane < 8) a1 += p[lane + 32];
    }
    OUT[(size_t)node * 40 + lane] = a0;
    if (lane < 8) OUT[(size_t)node * 40 + 32 + lane] = a1;
}

// ---------------------------------------------------------------------------
// launch
// ---------------------------------------------------------------------------
extern "C" void kernel_launch(void* const* d_in, const int* in_sizes, int n_in,
                              void* d_out, int out_size) {
    const float* x  = (const float*)d_in[0];
    const int*   ei = (const int*)d_in[1];     // int32 edge indices
    const float* W1 = (const float*)d_in[2];
    const float* W2 = (const float*)d_in[3];
    float* out = (float*)d_out;

    const int N = in_sizes[0] / 256;
    const int E = in_sizes[1] / 2;

    cudaFuncSetAttribute(gemm1_mma_kernel,
                         cudaFuncAttributeMaxDynamicSharedMemorySize, G1_SMEM);

    // CSR build
    zero_cnt_kernel<<<(NN + 255) / 256, 256>>>();
    hist_kernel<<<(E + 255) / 256, 256>>>(ei, E);
    scan1_kernel<<<NCHUNK, 256>>>();
    scan2_kernel<<<1, 32>>>(E);
    scan3_kernel<<<NCHUNK, 256>>>();
    build_kernel<<<(E + 255) / 256, 256>>>(ei, E);

    // layer 1
    wprep_kernel<<<128, 256>>>(W1);
    gemm1_mma_kernel<<<(N + 127) / 128, 256, G1_SMEM>>>(x, N);
    agg1_kernel<<<(NN + 7) / 8, 256>>>();

    // layer 2
    gemm2_kernel<<<(N + 63) / 64, 256>>>(W2, N);
    agg2_kernel<<<(NN + 7) / 8, 256>>>(out);
}